// round 3
// baseline (speedup 1.0000x reference)
#include <cuda_runtime.h>
#include <math.h>

#define BATCH 4
#define CC 64
#define HH 192
#define WW 192
#define NN (HH*WW)
#define NELEM (BATCH*CC*NN)

__device__ float g_scratch[(size_t)11 * NELEM];
__device__ float g_gram[512*1024];
__device__ float g_normp[512*64];
__device__ float g_attnw[8*1024];

typedef unsigned long long u64;

__device__ __forceinline__ u64 pack2(float a, float b){
  u64 r;
  asm("mov.b64 %0, {%1,%2};" : "=l"(r) : "r"(__float_as_uint(a)), "r"(__float_as_uint(b)));
  return r;
}
__device__ __forceinline__ void unpack2(u64 v, float &a, float &b){
  unsigned lo, hi;
  asm("mov.b64 {%0,%1}, %2;" : "=r"(lo), "=r"(hi) : "l"(v));
  a = __uint_as_float(lo); b = __uint_as_float(hi);
}
__device__ __forceinline__ void ffma2(u64 &d, u64 a, u64 b){
  asm("fma.rn.f32x2 %0, %1, %2, %0;" : "+l"(d) : "l"(a), "l"(b));
}
__device__ __forceinline__ float gelu_f(float x){
  return 0.5f*x*(1.0f + erff(x*0.70710678118654752f));
}

// ---- generic 64->64 conv1x1, 2 pixels/thread, all 64 outputs ----
__global__ void __launch_bounds__(256) k_conv64(
    const float* __restrict__ ext_in, int in_slice, int out_slice,
    const float* __restrict__ w, const float* __restrict__ bias)
{
  __shared__ float sw[64][64];   // sw[c][o]
  for (int idx = threadIdx.x; idx < 4096; idx += 256){
    int c = idx >> 6, o = idx & 63;
    sw[c][o] = w[o*64 + c];
  }
  __syncthreads();
  const float* xin = (in_slice >= 0) ? (g_scratch + (size_t)in_slice*NELEM) : ext_in;
  float* yout = g_scratch + (size_t)out_slice*NELEM;
  int gp = (blockIdx.x*256 + threadIdx.x) << 1;
  int b = gp / NN;
  int n = gp - b*NN;
  const float* xb = xin + (size_t)b*(CC*NN) + n;
  float* yb = yout + (size_t)b*(CC*NN) + n;
  u64 acc0[32], acc1[32];
  u64 z = pack2(0.f, 0.f);
  #pragma unroll
  for (int q = 0; q < 32; q++){ acc0[q] = z; acc1[q] = z; }
  #pragma unroll 4
  for (int c = 0; c < 64; c++){
    float2 xv = *(const float2*)(xb + (size_t)c*NN);
    u64 s0 = pack2(xv.x, xv.x);
    u64 s1 = pack2(xv.y, xv.y);
    const u64* wrow = (const u64*)(&sw[c][0]);
    #pragma unroll
    for (int q = 0; q < 32; q++){
      u64 wp = wrow[q];
      ffma2(acc0[q], wp, s0);
      ffma2(acc1[q], wp, s1);
    }
  }
  #pragma unroll
  for (int q = 0; q < 32; q++){
    float y00, y10, y01, y11;
    unpack2(acc0[q], y00, y10);
    unpack2(acc1[q], y01, y11);
    float b0 = bias ? bias[2*q]   : 0.f;
    float b1 = bias ? bias[2*q+1] : 0.f;
    *(float2*)(yb + (size_t)(2*q)*NN)   = make_float2(y00+b0, y01+b0);
    *(float2*)(yb + (size_t)(2*q+1)*NN) = make_float2(y10+b1, y11+b1);
  }
}

// ---- depthwise 3x3 + bias + exact GELU ----
__global__ void __launch_bounds__(256) k_dwgelu(
    int in_slice, int out_slice,
    const float* __restrict__ dw_w, const float* __restrict__ dw_b)
{
  int e = blockIdx.x*256 + threadIdx.x;
  const float* tin = g_scratch + (size_t)in_slice*NELEM;
  int n  = e % NN;
  int bc = e / NN;
  int c  = bc & 63;
  int h = n / WW, w = n - h*WW;
  const float* plane = tin + (size_t)bc*NN;
  float s = dw_b[c];
  #pragma unroll
  for (int ky = 0; ky < 3; ky++){
    int hh = h + ky - 1;
    if ((unsigned)hh >= (unsigned)HH) continue;
    #pragma unroll
    for (int kx = 0; kx < 3; kx++){
      int wx = w + kx - 1;
      if ((unsigned)wx >= (unsigned)WW) continue;
      s += dw_w[c*9 + ky*3 + kx] * plane[hh*WW + wx];
    }
  }
  g_scratch[(size_t)out_slice*NELEM + e] = gelu_f(s);
}

// ---- x1 = conv2 @ u + b2 + conv0 @ x + b0 ----
__global__ void __launch_bounds__(256) k_dual(
    const float* __restrict__ ext_x, int u_slice, int out_slice,
    const float* __restrict__ w2, const float* __restrict__ b2,
    const float* __restrict__ w0, const float* __restrict__ b0)
{
  __shared__ float swA[64][64];
  __shared__ float swB[64][64];
  for (int idx = threadIdx.x; idx < 4096; idx += 256){
    int c = idx >> 6, o = idx & 63;
    swA[c][o] = w2[o*64 + c];
    swB[c][o] = w0[o*64 + c];
  }
  __syncthreads();
  int gp = (blockIdx.x*256 + threadIdx.x) << 1;
  int b = gp / NN;
  int n = gp - b*NN;
  size_t boff = (size_t)b*(CC*NN) + n;
  const float* ub = g_scratch + (size_t)u_slice*NELEM + boff;
  const float* xb = ext_x + boff;
  float* yb = g_scratch + (size_t)out_slice*NELEM + boff;
  u64 acc0[32], acc1[32];
  u64 z = pack2(0.f, 0.f);
  #pragma unroll
  for (int q = 0; q < 32; q++){ acc0[q] = z; acc1[q] = z; }
  #pragma unroll 4
  for (int c = 0; c < 64; c++){
    float2 xv = *(const float2*)(ub + (size_t)c*NN);
    u64 s0 = pack2(xv.x, xv.x);
    u64 s1 = pack2(xv.y, xv.y);
    const u64* wrow = (const u64*)(&swA[c][0]);
    #pragma unroll
    for (int q = 0; q < 32; q++){
      ffma2(acc0[q], wrow[q], s0);
      ffma2(acc1[q], wrow[q], s1);
    }
  }
  #pragma unroll 4
  for (int c = 0; c < 64; c++){
    float2 xv = *(const float2*)(xb + (size_t)c*NN);
    u64 s0 = pack2(xv.x, xv.x);
    u64 s1 = pack2(xv.y, xv.y);
    const u64* wrow = (const u64*)(&swB[c][0]);
    #pragma unroll
    for (int q = 0; q < 32; q++){
      ffma2(acc0[q], wrow[q], s0);
      ffma2(acc1[q], wrow[q], s1);
    }
  }
  #pragma unroll
  for (int q = 0; q < 32; q++){
    float y00, y10, y01, y11;
    unpack2(acc0[q], y00, y10);
    unpack2(acc1[q], y01, y11);
    float bb0 = b2[2*q]   + b0[2*q];
    float bb1 = b2[2*q+1] + b0[2*q+1];
    *(float2*)(yb + (size_t)(2*q)*NN)   = make_float2(y00+bb0, y01+bb0);
    *(float2*)(yb + (size_t)(2*q+1)*NN) = make_float2(y10+bb1, y11+bb1);
  }
}

// ---- split-K gram + squared norms (channel attention), blk=(b*2+g)*64+s ----
__global__ void __launch_bounds__(256) k_gram(int q_slice, int k_slice)
{
  int blk = blockIdx.x;
  int s  = blk & 63;
  int bg = blk >> 6;
  int g = bg & 1, b = bg >> 1;
  int n0 = s * 576;
  const float* qb = g_scratch + (size_t)q_slice*NELEM + (size_t)(b*64 + g*32)*NN;
  const float* kb = g_scratch + (size_t)k_slice*NELEM + (size_t)(b*64 + g*32)*NN;
  __shared__ float qs[32][65];
  __shared__ float ks[32][65];
  int t = threadIdx.x;
  int i = t & 31, jb = t >> 5;
  float acc[4] = {0.f,0.f,0.f,0.f};
  float nacc = 0.f;
  for (int ch = 0; ch < 9; ch++){
    int nb = n0 + ch*64;
    __syncthreads();
    for (int idx = t; idx < 2048; idx += 256){
      int r = idx >> 6, nn = idx & 63;
      qs[r][nn] = qb[(size_t)r*NN + nb + nn];
      ks[r][nn] = kb[(size_t)r*NN + nb + nn];
    }
    __syncthreads();
    #pragma unroll 8
    for (int nn = 0; nn < 64; nn++){
      float qv = qs[i][nn];
      acc[0] += qv * ks[jb*4+0][nn];
      acc[1] += qv * ks[jb*4+1][nn];
      acc[2] += qv * ks[jb*4+2][nn];
      acc[3] += qv * ks[jb*4+3][nn];
    }
    if (t < 32){
      #pragma unroll 8
      for (int nn = 0; nn < 64; nn++){ float v = qs[t][nn]; nacc += v*v; }
    } else if (t < 64){
      int r = t - 32;
      #pragma unroll 8
      for (int nn = 0; nn < 64; nn++){ float v = ks[r][nn]; nacc += v*v; }
    }
  }
  float* Gp = g_gram + (size_t)blk*1024;
  #pragma unroll
  for (int jj = 0; jj < 4; jj++) Gp[i*32 + jb*4 + jj] = acc[jj];
  if (t < 64) g_normp[(size_t)blk*64 + t] = nacc;
}

// ---- finalize: normalize + temperature + row softmax. blk=b*2+g ----
__global__ void __launch_bounds__(1024) k_attnsoft(const float* __restrict__ temperature)
{
  int bg = blockIdx.x;
  int g = bg & 1;
  int t = threadIdx.x;
  int i = t >> 5, j = t & 31;
  __shared__ float nq[32], nk[32];
  if (t < 64){
    float s = 0.f;
    for (int ss = 0; ss < 64; ss++) s += g_normp[(size_t)(bg*64 + ss)*64 + t];
    float nv = fmaxf(sqrtf(s), 1e-12f);
    if (t < 32) nq[t] = nv; else nk[t-32] = nv;
  }
  float G = 0.f;
  for (int ss = 0; ss < 64; ss++) G += g_gram[(size_t)(bg*64 + ss)*1024 + t];
  __syncthreads();
  float logit = G / (nq[i]*nk[j]) * temperature[g];
  float m = logit;
  #pragma unroll
  for (int o = 16; o > 0; o >>= 1) m = fmaxf(m, __shfl_xor_sync(0xffffffffu, m, o));
  float e = __expf(logit - m);
  float ssum = e;
  #pragma unroll
  for (int o = 16; o > 0; o >>= 1) ssum += __shfl_xor_sync(0xffffffffu, ssum, o);
  g_attnw[(size_t)bg*1024 + t] = e / ssum;
}

// ---- apply channel attention: tmp = blockdiag(attn) @ v ----
__global__ void __launch_bounds__(256) k_apply(int v_slice, int out_slice)
{
  __shared__ float saw[2][32][32];     // saw[g][j][i] = attn[b,g,i,j]
  int gp = (blockIdx.x*256 + threadIdx.x) << 1;
  int b = gp / NN;
  int n = gp - b*NN;
  for (int idx = threadIdx.x; idx < 2048; idx += 256){
    int gg = idx >> 10;
    int rem = idx & 1023;
    int i = rem & 31, j = rem >> 5;
    saw[gg][j][i] = g_attnw[(size_t)(b*2+gg)*1024 + i*32 + j];
  }
  __syncthreads();
  const float* vb = g_scratch + (size_t)v_slice*NELEM + (size_t)b*(CC*NN) + n;
  float* yb = g_scratch + (size_t)out_slice*NELEM + (size_t)b*(CC*NN) + n;
  u64 acc0[32], acc1[32];
  u64 z = pack2(0.f, 0.f);
  #pragma unroll
  for (int q = 0; q < 32; q++){ acc0[q] = z; acc1[q] = z; }
  for (int gg = 0; gg < 2; gg++){
    #pragma unroll 4
    for (int j = 0; j < 32; j++){
      float2 xv = *(const float2*)(vb + (size_t)(gg*32 + j)*NN);
      u64 s0 = pack2(xv.x, xv.x);
      u64 s1 = pack2(xv.y, xv.y);
      const u64* wrow = (const u64*)(&saw[gg][j][0]);
      #pragma unroll
      for (int q = 0; q < 16; q++){
        ffma2(acc0[gg*16 + q], wrow[q], s0);
        ffma2(acc1[gg*16 + q], wrow[q], s1);
      }
    }
  }
  #pragma unroll
  for (int q = 0; q < 32; q++){
    float y00, y10, y01, y11;
    unpack2(acc0[q], y00, y10);
    unpack2(acc1[q], y01, y11);
    *(float2*)(yb + (size_t)(2*q)*NN)   = make_float2(y00, y01);
    *(float2*)(yb + (size_t)(2*q+1)*NN) = make_float2(y10, y11);
  }
}

// ---- line attention (row; col via transposed planes). CTA per (b,line) ----
__global__ void __launch_bounds__(192, 2) k_lineattn(
    int q_slice, int k_slice, int v_slice, int x_slice, int out_slice,
    const float* __restrict__ gamma_p)
{
  extern __shared__ float smem[];
  float* Ksh = smem;                 // [192][66], j-major
  float* Vsh = smem + 192*66;
  int blk = blockIdx.x;
  int h = blk % HH;
  int b = blk / HH;
  size_t base = (size_t)b*(CC*NN) + (size_t)h*WW;
  const float* Qb = g_scratch + (size_t)q_slice*NELEM + base;
  const float* Kb = g_scratch + (size_t)k_slice*NELEM + base;
  const float* Vb = g_scratch + (size_t)v_slice*NELEM + base;
  const float* Xb = g_scratch + (size_t)x_slice*NELEM + base;
  float* Ob = g_scratch + (size_t)out_slice*NELEM + base;
  int t = threadIdx.x;
  for (int idx = t; idx < 64*192; idx += 192){
    int c = idx / 192;
    int j = idx - c*192;
    Ksh[j*66 + c] = Kb[(size_t)c*NN + j];
    Vsh[j*66 + c] = Vb[(size_t)c*NN + j];
  }
  u64 q2[32];
  #pragma unroll
  for (int cc = 0; cc < 32; cc++)
    q2[cc] = pack2(Qb[(size_t)(2*cc)*NN + t], Qb[(size_t)(2*cc+1)*NN + t]);
  __syncthreads();
  u64 z = pack2(0.f, 0.f);
  float sv[192];
  float m = -1e30f;
  #pragma unroll 1
  for (int j = 0; j < 192; j++){
    const u64* kr = (const u64*)(Ksh + j*66);
    u64 a0 = z, a1 = z, a2 = z, a3 = z;
    #pragma unroll
    for (int cc = 0; cc < 8; cc++){
      ffma2(a0, q2[4*cc+0], kr[4*cc+0]);
      ffma2(a1, q2[4*cc+1], kr[4*cc+1]);
      ffma2(a2, q2[4*cc+2], kr[4*cc+2]);
      ffma2(a3, q2[4*cc+3], kr[4*cc+3]);
    }
    float x0,y0,x1,y1,x2,y2,x3,y3;
    unpack2(a0,x0,y0); unpack2(a1,x1,y1); unpack2(a2,x2,y2); unpack2(a3,x3,y3);
    float s = ((x0+y0)+(x1+y1)) + ((x2+y2)+(x3+y3));
    sv[j] = s;
    m = fmaxf(m, s);
  }
  float l = 0.f;
  u64 acc[32];
  #pragma unroll
  for (int cc = 0; cc < 32; cc++) acc[cc] = z;
  #pragma unroll 1
  for (int j = 0; j < 192; j++){
    float p = __expf(sv[j] - m);
    l += p;
    u64 ps = pack2(p, p);
    const u64* vr = (const u64*)(Vsh + j*66);
    #pragma unroll
    for (int cc = 0; cc < 32; cc++) ffma2(acc[cc], ps, vr[cc]);
  }
  float gam = gamma_p[0] / l;
  #pragma unroll
  for (int cc = 0; cc < 32; cc++){
    float a0, a1; unpack2(acc[cc], a0, a1);
    Ob[(size_t)(2*cc)*NN + t]   = gam*a0 + Xb[(size_t)(2*cc)*NN + t];
    Ob[(size_t)(2*cc+1)*NN + t] = gam*a1 + Xb[(size_t)(2*cc+1)*NN + t];
  }
}

// ---- per-plane 192x192 transpose ----
__global__ void k_transpose(int in_slice, int out_slice)
{
  __shared__ float tile[32][33];
  const float* in = g_scratch + (size_t)in_slice*NELEM + (size_t)blockIdx.z*NN;
  float* out      = g_scratch + (size_t)out_slice*NELEM + (size_t)blockIdx.z*NN;
  int x0 = blockIdx.x*32, y0 = blockIdx.y*32;
  int tx = threadIdx.x, ty = threadIdx.y;
  #pragma unroll
  for (int k = 0; k < 32; k += 8)
    tile[ty+k][tx] = in[(size_t)(y0+ty+k)*WW + x0+tx];
  __syncthreads();
  #pragma unroll
  for (int k = 0; k < 32; k += 8)
    out[(size_t)(x0+ty+k)*HH + y0+tx] = tile[tx][ty+k];
}

// ---- final fuse conv: gelu(conv_w @ [o1;o2;o3] + b) -> d_out ----
__global__ void __launch_bounds__(256) k_final(
    int s1, int s2, int s3,
    const float* __restrict__ w, const float* __restrict__ bias,
    float* __restrict__ out)
{
  __shared__ float sw[192][64];          // sw[cin][o]
  for (int idx = threadIdx.x; idx < 192*64; idx += 256){
    int cin = idx >> 6, o = idx & 63;
    sw[cin][o] = w[o*192 + cin];
  }
  __syncthreads();
  int gp = (blockIdx.x*256 + threadIdx.x) << 1;
  int b = gp / NN;
  int n = gp - b*NN;
  size_t boff = (size_t)b*(CC*NN) + n;
  u64 acc0[32], acc1[32];
  u64 z = pack2(0.f, 0.f);
  #pragma unroll
  for (int q = 0; q < 32; q++){ acc0[q] = z; acc1[q] = z; }
  int slices[3] = {s1, s2, s3};
  for (int part = 0; part < 3; part++){
    const float* xb = g_scratch + (size_t)slices[part]*NELEM + boff;
    #pragma unroll 4
    for (int c = 0; c < 64; c++){
      float2 xv = *(const float2*)(xb + (size_t)c*NN);
      u64 s0 = pack2(xv.x, xv.x);
      u64 s1v = pack2(xv.y, xv.y);
      const u64* wrow = (const u64*)(&sw[part*64 + c][0]);
      #pragma unroll
      for (int q = 0; q < 32; q++){
        ffma2(acc0[q], wrow[q], s0);
        ffma2(acc1[q], wrow[q], s1v);
      }
    }
  }
  float* yb = out + boff;
  #pragma unroll
  for (int q = 0; q < 32; q++){
    float y00, y10, y01, y11;
    unpack2(acc0[q], y00, y10);
    unpack2(acc1[q], y01, y11);
    float b0 = bias[2*q], b1 = bias[2*q+1];
    *(float2*)(yb + (size_t)(2*q)*NN)   = make_float2(gelu_f(y00+b0), gelu_f(y01+b0));
    *(float2*)(yb + (size_t)(2*q+1)*NN) = make_float2(gelu_f(y10+b1), gelu_f(y11+b1));
  }
}

extern "C" void kernel_launch(void* const* d_in, const int* in_sizes, int n_in,
                              void* d_out, int out_size)
{
  const float* x    = (const float*)d_in[0];
  const float* pw_w = (const float*)d_in[1];
  const float* dw_w = (const float*)d_in[2];
  const float* dw_b = (const float*)d_in[3];
  const float* c2w  = (const float*)d_in[4];
  const float* c2b  = (const float*)d_in[5];
  const float* c0w  = (const float*)d_in[6];
  const float* c0b  = (const float*)d_in[7];
  const float* aq   = (const float*)d_in[8];
  const float* ak   = (const float*)d_in[9];
  const float* av   = (const float*)d_in[10];
  const float* ap   = (const float*)d_in[11];
  const float* temp = (const float*)d_in[12];
  const float* rq   = (const float*)d_in[13];
  const float* rk   = (const float*)d_in[14];
  const float* rv   = (const float*)d_in[15];
  const float* rg   = (const float*)d_in[16];
  const float* cq   = (const float*)d_in[17];
  const float* ck   = (const float*)d_in[18];
  const float* cv   = (const float*)d_in[19];
  const float* cg   = (const float*)d_in[20];
  const float* fw   = (const float*)d_in[21];
  const float* fb   = (const float*)d_in[22];
  float* out = (float*)d_out;

  const int PB = (BATCH*NN/2)/256;            // 288 blocks
  const int SMEM_LA = 2*192*66*4;             // 101376 B
  cudaFuncSetAttribute(k_lineattn, cudaFuncAttributeMaxDynamicSharedMemorySize, SMEM_LA);

  k_conv64<<<PB,256>>>(x, -1, 0, pw_w, nullptr);          // t = pw(x)
  k_dwgelu<<<NELEM/256,256>>>(0, 1, dw_w, dw_b);          // gelu(dw(t)+b)
  k_dual<<<PB,256>>>(x, 1, 2, c2w, c2b, c0w, c0b);        // x1

  k_conv64<<<PB,256>>>(nullptr, 2, 3, aq, nullptr);       // Q
  k_conv64<<<PB,256>>>(nullptr, 2, 4, ak, nullptr);       // K
  k_conv64<<<PB,256>>>(nullptr, 2, 5, av, nullptr);       // V
  k_gram<<<512,256>>>(3, 4);
  k_attnsoft<<<8,1024>>>(temp);
  k_apply<<<PB,256>>>(5, 6);
  k_conv64<<<PB,256>>>(nullptr, 6, 7, ap, nullptr);       // out1

  k_conv64<<<PB,256>>>(nullptr, 2, 3, rq, nullptr);
  k_conv64<<<PB,256>>>(nullptr, 2, 4, rk, nullptr);
  k_conv64<<<PB,256>>>(nullptr, 7, 5, rv, nullptr);       // V from out1
  k_lineattn<<<768,192,SMEM_LA>>>(3, 4, 5, 2, 8, rg);     // out2

  k_conv64<<<PB,256>>>(nullptr, 2, 3, cq, nullptr);
  k_conv64<<<PB,256>>>(nullptr, 2, 4, ck, nullptr);
  k_conv64<<<PB,256>>>(nullptr, 7, 5, cv, nullptr);       // V from out1
  dim3 tg(6,6,BATCH*CC), tb(32,8);
  k_transpose<<<tg,tb>>>(3, 0);
  k_transpose<<<tg,tb>>>(4, 1);
  k_transpose<<<tg,tb>>>(5, 6);
  k_transpose<<<tg,tb>>>(2, 10);
  k_lineattn<<<768,192,SMEM_LA>>>(0, 1, 6, 10, 3, cg);    // out3^T
  k_transpose<<<tg,tb>>>(3, 9);                           // out3

  k_final<<<PB,256>>>(7, 8, 9, fw, fb, out);
}